// round 2
// baseline (speedup 1.0000x reference)
#include <cuda_runtime.h>
#include <cstdint>

#define D_ 64
#define B_ 64
#define S_ 1024
#define L_ 512
#define O_ 10

#define NST 3
#define SITE_BYTES 32768            // one site: 64*64*2 floats
#define STAGE_BYTES 65536           // 2 sites per stage
#define CLUSTER 8
#define SLICE_BYTES (STAGE_BYTES / CLUSTER)   // 8192 per rank
#define NPAIRS 256

#define CONS_THREADS 128
#define TOTAL_THREADS 160

// dynamic smem layout
#define OFF_STAGE 0
#define OFF_X     (NST * STAGE_BYTES)          // 196608: float2 xsh[512]
#define OFF_V     (OFF_X + 4096)               // float vbuf[2][64]
#define OFF_MBAR  (OFF_V + 512)                // full[3] @ +0, empty[3] @ +24
#define SMEM_TOTAL (OFF_MBAR + 64)

__device__ float g_vL[B_][D_];
__device__ float g_wR[B_][D_];

// ---------- PTX helpers ----------
__device__ __forceinline__ uint32_t smem_u32(const void* p) {
    uint32_t a;
    asm("{ .reg .u64 t; cvta.to.shared.u64 t, %1; cvt.u32.u64 %0, t; }" : "=r"(a) : "l"(p));
    return a;
}
__device__ __forceinline__ uint32_t ctarank() {
    uint32_t r; asm("mov.u32 %0, %%cluster_ctarank;" : "=r"(r)); return r;
}
__device__ __forceinline__ uint32_t elect_one() {
    uint32_t p;
    asm volatile("{ .reg .pred p; elect.sync _|p, 0xFFFFFFFF; selp.b32 %0, 1, 0, p; }" : "=r"(p));
    return p;
}
#define MBARRIER_INIT(addr, cnt) \
    asm volatile("mbarrier.init.shared.b64 [%0], %1;" :: "r"(addr), "r"((uint32_t)(cnt)) : "memory")
#define MBARRIER_EXPECT_TX(addr, tx) \
    asm volatile("mbarrier.arrive.expect_tx.shared.b64 _, [%0], %1;" :: "r"(addr), "r"((uint32_t)(tx)) : "memory")
#define MBARRIER_ARRIVE_CLUSTER(addr, trank) \
    asm volatile("{ .reg .b32 ra; mapa.shared::cluster.u32 ra, %0, %1; " \
                 "mbarrier.arrive.shared::cluster.b64 _, [ra]; }" \
                 :: "r"((uint32_t)(addr)), "r"((uint32_t)(trank)) : "memory")
#define MBARRIER_WAIT_PARITY(addr, par) do { \
    uint32_t _m = (addr), _p = (par), _d; \
    asm volatile("{ .reg .pred p; mbarrier.try_wait.parity.acquire.cta.shared::cta.b64 p, [%1], %2; " \
                 "selp.b32 %0, 1, 0, p; }" : "=r"(_d) : "r"(_m), "r"(_p) : "memory"); \
    if (!_d) { \
        asm volatile("{ .reg .pred P1; WL_%=: mbarrier.try_wait.parity.acquire.cta.shared::cta.b64 P1, [%0], %1, 0x989680; " \
                     "@P1 bra.uni WD_%=; bra.uni WL_%=; WD_%=: }" :: "r"(_m), "r"(_p) : "memory"); \
    } } while (0)
#define MBARRIER_WAIT_PARITY_RELAXED(addr, par) do { \
    uint32_t _m = (addr), _p = (par), _d; \
    asm volatile("{ .reg .pred p; mbarrier.try_wait.parity.relaxed.cta.shared::cta.b64 p, [%1], %2, 0x989680; " \
                 "selp.b32 %0, 1, 0, p; }" : "=r"(_d) : "r"(_m), "r"(_p) : "memory"); \
    if (!_d) { \
        asm volatile("{ .reg .pred P1; WL_%=: mbarrier.try_wait.parity.relaxed.cta.shared::cta.b64 P1, [%0], %1, 0x989680; " \
                     "@P1 bra.uni WD_%=; bra.uni WL_%=; WD_%=: }" :: "r"(_m), "r"(_p) : "memory"); \
    } } while (0)
#define BULK_MC(dst, src, bytes, mbar, mask) \
    asm volatile("cp.async.bulk.shared::cluster.global.mbarrier::complete_tx::bytes.multicast::cluster " \
                 "[%0], [%1], %2, [%3], %4;" \
                 :: "r"((uint32_t)(dst)), "l"(src), "r"((uint32_t)(bytes)), \
                    "r"((uint32_t)(mbar)), "h"((uint16_t)(mask)) : "memory")
#define NAMED_BAR(id, n) asm volatile("bar.sync %0, %1;" :: "r"(id), "r"(n) : "memory")
#define CLUSTER_SYNC() do { \
    asm volatile("barrier.cluster.arrive.aligned;" ::: "memory"); \
    asm volatile("barrier.cluster.wait.aligned;"   ::: "memory"); } while (0)

// ---------- chain kernel ----------
// grid 128 linear: side = bx>>6, batch = bx&63. Cluster of 8 consecutive CTAs
// (same side, 8 batches) shares the W stream via bulk-copy multicast.
__global__ void __launch_bounds__(TOTAL_THREADS, 1)
chain_kernel(const float* __restrict__ x, const float* __restrict__ Wl,
             const float* __restrict__ Wr) {
    extern __shared__ char smem[];
    uint32_t sb = smem_u32(smem);
    int tid = threadIdx.x;
    int bx = blockIdx.x;
    int side = bx >> 6;
    int b = bx & 63;
    uint32_t rank = ctarank();

    uint32_t mb_full  = sb + OFF_MBAR;
    uint32_t mb_empty = sb + OFF_MBAR + 24;

    if (tid == 0) {
        #pragma unroll
        for (int i = 0; i < NST; i++) {
            MBARRIER_INIT(mb_full  + 8 * i, 1);
            MBARRIER_INIT(mb_empty + 8 * i, CLUSTER);
        }
    }
    // stage this CTA's x slice and init v
    float2* xsh = (float2*)(smem + OFF_X);
    const float2* xsrc = (const float2*)x + (size_t)b * S_ + side * L_;
    for (int i = tid; i < L_; i += TOTAL_THREADS) xsh[i] = xsrc[i];
    float* vbuf = (float*)(smem + OFF_V);
    if (tid < 64) vbuf[tid] = (tid == 0) ? 1.0f : 0.0f;
    __syncthreads();
    CLUSTER_SYNC();   // all mbarriers visible before any multicast

    if (tid >= CONS_THREADS) {
        // ---- producer warp (whole warp stays converged; elect-one issues) ----
        const char* Wb = (const char*)(side ? Wr : Wl);
        int slot = 0, ph = 1;
        for (int P = 0; P < NPAIRS; P++) {
            MBARRIER_WAIT_PARITY_RELAXED(mb_empty + 8 * slot, ph);
            long rowbase = side ? (long)(510 - 2 * P) : (long)(2 * P);
            const char* src = Wb + rowbase * (long)SITE_BYTES + rank * SLICE_BYTES;
            uint32_t dst = sb + OFF_STAGE + slot * STAGE_BYTES + rank * SLICE_BYTES;
            if (elect_one()) {
                MBARRIER_EXPECT_TX(mb_full + 8 * slot, STAGE_BYTES);
                BULK_MC(dst, src, SLICE_BYTES, mb_full + 8 * slot, 0xFF);
            }
            if (++slot == NST) { slot = 0; ph ^= 1; }
        }
    } else {
        // ---- 128 consumer threads: o = output index, h = dot-half ----
        int h = tid & 1;
        int o = tid >> 1;
        int slot = 0, ph = 0;
        for (int P = 0; P < NPAIRS; P++) {
            MBARRIER_WAIT_PARITY(mb_full + 8 * slot, ph);
            #pragma unroll
            for (int sub = 0; sub < 2; sub++) {
                int s = 2 * P + sub;
                int j = side ? (511 - s) : s;                 // W row & x index
                int sip = side ? (1 - sub) : sub;             // slot-in-pair
                const float2* Wst = (const float2*)(smem + OFF_STAGE +
                                    slot * STAGE_BYTES + sip * SITE_BYTES);
                const float* vc = vbuf + (s & 1) * 64;
                float*       vn = vbuf + ((s & 1) ^ 1) * 64;
                float2 xs = xsh[j];
                float cx = 0.f, cy = 0.f;
                if (side == 0) {
                    // v'[r] : dot over l, W[l][(r,i)] strided
                    const float4* v4 = (const float4*)vc + 8 * h;
                    #pragma unroll
                    for (int q = 0; q < 8; q++) {
                        float4 vq = v4[q];
                        int l0 = 32 * h + 4 * q;
                        float2 w0 = Wst[(l0 + 0) * 64 + o];
                        float2 w1 = Wst[(l0 + 1) * 64 + o];
                        float2 w2 = Wst[(l0 + 2) * 64 + o];
                        float2 w3 = Wst[(l0 + 3) * 64 + o];
                        cx += vq.x * w0.x + vq.y * w1.x + vq.z * w2.x + vq.w * w3.x;
                        cy += vq.x * w0.y + vq.y * w1.y + vq.z * w2.y + vq.w * w3.y;
                    }
                } else {
                    // w'[l] : dot over r, W[l][(r,i)] contiguous; lane-rotated
                    int rot = o & 7;
                    const float4* w4 = (const float4*)vc;
                    #pragma unroll
                    for (int jj = 0; jj < 8; jj++) {
                        int q = (jj + rot) & 7;
                        int r0 = 32 * h + 4 * q;
                        float4 wq = w4[r0 >> 2];
                        float4 Wa = *(const float4*)(&Wst[o * 64 + r0]);
                        float4 Wc = *(const float4*)(&Wst[o * 64 + r0 + 2]);
                        cx += wq.x * Wa.x + wq.y * Wa.z + wq.z * Wc.x + wq.w * Wc.z;
                        cy += wq.x * Wa.y + wq.y * Wa.w + wq.z * Wc.y + wq.w * Wc.w;
                    }
                }
                cx += __shfl_xor_sync(0xFFFFFFFFu, cx, 1);
                cy += __shfl_xor_sync(0xFFFFFFFFu, cy, 1);
                if (h == 0) vn[o] = xs.x * cx + xs.y * cy;
                NAMED_BAR(1, CONS_THREADS);
            }
            if (tid == 0) {   // stage fully consumed (post-barrier): release everywhere
                #pragma unroll
                for (int k = 0; k < CLUSTER; k++)
                    MBARRIER_ARRIVE_CLUSTER(mb_empty + 8 * slot, k);
            }
            if (++slot == NST) { slot = 0; ph ^= 1; }
        }
        if (tid < 64) {      // after 512 sites result sits in vbuf[0]
            if (side) g_wR[b][tid] = vbuf[tid];
            else      g_vL[b][tid] = vbuf[tid];
        }
    }
    CLUSTER_SYNC();          // no CTA exits while peer multicast may target it
}

// ---------- output contraction ----------
__global__ void output_kernel(const float* __restrict__ core, float* __restrict__ out) {
    int b = blockIdx.x;
    int l = threadIdx.x;                 // 64 threads
    __shared__ float wsh[D_];
    __shared__ float red[D_];
    wsh[l] = g_wR[b][l];
    float vl = g_vL[b][l];
    __syncthreads();
    for (int o = 0; o < O_; o++) {
        const float* c = core + (o * D_ + l) * D_;
        float s0 = 0.f, s1 = 0.f;
        #pragma unroll 8
        for (int rr = 0; rr < D_; rr += 2) {
            s0 += c[rr] * wsh[rr];
            s1 += c[rr + 1] * wsh[rr + 1];
        }
        red[l] = vl * (s0 + s1);
        __syncthreads();
        for (int off = 32; off > 0; off >>= 1) {
            if (l < off) red[l] += red[l + off];
            __syncthreads();
        }
        if (l == 0) out[b * O_ + o] = red[0];
        __syncthreads();
    }
}

extern "C" void kernel_launch(void* const* d_in, const int* in_sizes, int n_in,
                              void* d_out, int out_size) {
    const float* x    = (const float*)d_in[0];   // [64, 1024, 2]
    const float* Wl   = (const float*)d_in[1];   // [512, 64, 64, 2]
    const float* core = (const float*)d_in[2];   // [10, 64, 64]
    const float* Wr   = (const float*)d_in[3];   // [512, 64, 64, 2]
    float* out = (float*)d_out;                  // [64, 10]

    cudaFuncSetAttribute(chain_kernel,
                         cudaFuncAttributeMaxDynamicSharedMemorySize, SMEM_TOTAL);

    cudaLaunchConfig_t cfg = {};
    cfg.gridDim = dim3(128, 1, 1);
    cfg.blockDim = dim3(TOTAL_THREADS, 1, 1);
    cfg.dynamicSmemBytes = SMEM_TOTAL;
    cfg.stream = 0;
    cudaLaunchAttribute at[1];
    at[0].id = cudaLaunchAttributeClusterDimension;
    at[0].val.clusterDim.x = CLUSTER;
    at[0].val.clusterDim.y = 1;
    at[0].val.clusterDim.z = 1;
    cfg.attrs = at;
    cfg.numAttrs = 1;
    cudaLaunchKernelEx(&cfg, chain_kernel, x, Wl, Wr);

    output_kernel<<<B_, 64>>>(core, out);
}

// round 3
// speedup vs baseline: 3.2535x; 3.2535x over previous
#include <cuda_runtime.h>
#include <cstdint>

#define D_ 64
#define B_ 64
#define S_ 1024
#define L_ 512
#define O_ 10

#define NST 3
#define SITE_BYTES 32768                     // 64*64*2 floats
#define STAGE_BYTES 65536                    // 2 sites / stage
#define CLUSTER 4
#define SLICE_BYTES (STAGE_BYTES / CLUSTER)  // 16384 per rank
#define NPAIRS 256

#define CONS 256
#define TOT 288

// dynamic smem layout
#define OFF_X   (NST * STAGE_BYTES)          // 196608: float2 xsh[512]
#define OFF_V   (OFF_X + 4096)               // float vbuf[2][64]
#define OFF_P   (OFF_V + 512)                // float2 part[4][64]
#define OFF_MB  (OFF_P + 2048)               // full[3] @ +0, empty[3] @ +24
#define SMEM_TOTAL (OFF_MB + 64)

__device__ float g_vL[B_][D_];
__device__ float g_wR[B_][D_];
__device__ float g_WrT[L_ * D_ * D_ * 2];    // transposed + site-reversed W_right

// ---------- PTX helpers ----------
__device__ __forceinline__ uint32_t smem_u32(const void* p) {
    uint32_t a;
    asm("{ .reg .u64 t; cvta.to.shared.u64 t, %1; cvt.u32.u64 %0, t; }" : "=r"(a) : "l"(p));
    return a;
}
__device__ __forceinline__ uint32_t ctarank() {
    uint32_t r; asm("mov.u32 %0, %%cluster_ctarank;" : "=r"(r)); return r;
}
__device__ __forceinline__ uint32_t elect_one() {
    uint32_t p;
    asm volatile("{ .reg .pred p; elect.sync _|p, 0xFFFFFFFF; selp.b32 %0, 1, 0, p; }" : "=r"(p));
    return p;
}
#define MBARRIER_INIT(addr, cnt) \
    asm volatile("mbarrier.init.shared.b64 [%0], %1;" :: "r"(addr), "r"((uint32_t)(cnt)) : "memory")
#define MBARRIER_EXPECT_TX(addr, tx) \
    asm volatile("mbarrier.arrive.expect_tx.shared.b64 _, [%0], %1;" :: "r"(addr), "r"((uint32_t)(tx)) : "memory")
#define MBARRIER_ARRIVE_CLUSTER(addr, trank) \
    asm volatile("{ .reg .b32 ra; mapa.shared::cluster.u32 ra, %0, %1; " \
                 "mbarrier.arrive.shared::cluster.b64 _, [ra]; }" \
                 :: "r"((uint32_t)(addr)), "r"((uint32_t)(trank)) : "memory")
#define MBARRIER_WAIT_PARITY(addr, par) do { \
    uint32_t _m = (addr), _p = (par), _d; \
    asm volatile("{ .reg .pred p; mbarrier.try_wait.parity.acquire.cta.shared::cta.b64 p, [%1], %2; " \
                 "selp.b32 %0, 1, 0, p; }" : "=r"(_d) : "r"(_m), "r"(_p) : "memory"); \
    if (!_d) { \
        asm volatile("{ .reg .pred P1; WL_%=: mbarrier.try_wait.parity.acquire.cta.shared::cta.b64 P1, [%0], %1, 0x989680; " \
                     "@P1 bra.uni WD_%=; bra.uni WL_%=; WD_%=: }" :: "r"(_m), "r"(_p) : "memory"); \
    } } while (0)
#define MBARRIER_WAIT_PARITY_RELAXED(addr, par) do { \
    uint32_t _m = (addr), _p = (par), _d; \
    asm volatile("{ .reg .pred p; mbarrier.try_wait.parity.relaxed.cta.shared::cta.b64 p, [%1], %2, 0x989680; " \
                 "selp.b32 %0, 1, 0, p; }" : "=r"(_d) : "r"(_m), "r"(_p) : "memory"); \
    if (!_d) { \
        asm volatile("{ .reg .pred P1; WL_%=: mbarrier.try_wait.parity.relaxed.cta.shared::cta.b64 P1, [%0], %1, 0x989680; " \
                     "@P1 bra.uni WD_%=; bra.uni WL_%=; WD_%=: }" :: "r"(_m), "r"(_p) : "memory"); \
    } } while (0)
#define BULK_MC(dst, src, bytes, mbar, mask) \
    asm volatile("cp.async.bulk.shared::cluster.global.mbarrier::complete_tx::bytes.multicast::cluster " \
                 "[%0], [%1], %2, [%3], %4;" \
                 :: "r"((uint32_t)(dst)), "l"(src), "r"((uint32_t)(bytes)), \
                    "r"((uint32_t)(mbar)), "h"((uint16_t)(mask)) : "memory")
#define NAMED_BAR(id, n) asm volatile("bar.sync %0, %1;" :: "r"(id), "r"(n) : "memory")
#define CLUSTER_SYNC() do { \
    asm volatile("barrier.cluster.arrive.aligned;" ::: "memory"); \
    asm volatile("barrier.cluster.wait.aligned;"   ::: "memory"); } while (0)

// ---------- transpose (right side -> left-side access pattern) ----------
// WrT[u][r][l][i] = W_right[(L-1)-u][l][r][i]
__global__ void transpose_wr_kernel(const float* __restrict__ Wr) {
    int u = blockIdx.x;
    int t = (L_ - 1) - u;
    const float2* src = (const float2*)(Wr) + t * (D_ * D_);
    float2* dst = (float2*)(g_WrT) + u * (D_ * D_);
    __shared__ float2 tile[D_ * (D_ + 1)];
    for (int idx = threadIdx.x; idx < D_ * D_; idx += blockDim.x) {
        int l = idx >> 6, r = idx & 63;
        tile[r * (D_ + 1) + l] = src[idx];
    }
    __syncthreads();
    for (int idx = threadIdx.x; idx < D_ * D_; idx += blockDim.x) {
        int rr = idx >> 6, ll = idx & 63;
        dst[idx] = tile[rr * (D_ + 1) + ll];
    }
}

// ---------- chain kernel ----------
// grid 128: side = bx>>6, b = bx&63. Cluster of 4 consecutive CTAs (same side)
// shares the W stream via sliced bulk-copy multicast into a 3-stage smem ring.
__global__ void __launch_bounds__(TOT, 1)
chain_kernel(const float* __restrict__ x, const float* __restrict__ Wl) {
    extern __shared__ char smem[];
    uint32_t sb = smem_u32(smem);
    int tid = threadIdx.x;
    int bx = blockIdx.x;
    int side = bx >> 6;
    int b = bx & 63;
    uint32_t rank = ctarank();

    uint32_t mb_full  = sb + OFF_MB;
    uint32_t mb_empty = sb + OFF_MB + 24;

    if (tid == 0) {
        #pragma unroll
        for (int i = 0; i < NST; i++) {
            MBARRIER_INIT(mb_full  + 8 * i, 1);
            MBARRIER_INIT(mb_empty + 8 * i, CLUSTER);
        }
    }
    float2* xsh = (float2*)(smem + OFF_X);
    const float2* xsrc = (const float2*)x + (size_t)b * S_ + side * L_;
    for (int i = tid; i < L_; i += TOT) xsh[i] = xsrc[i];
    float* vb = (float*)(smem + OFF_V);
    if (tid < 64) vb[tid] = (tid == 0) ? 1.0f : 0.0f;
    __syncthreads();
    CLUSTER_SYNC();     // mbarriers visible before any multicast

    if (tid >= CONS) {
        // ---- producer warp: stream 2-site stages, 16KB slice per rank ----
        const char* Wb = side ? (const char*)g_WrT : (const char*)Wl;
        int slot = 0, ph = 1;
        for (int P = 0; P < NPAIRS; P++) {
            MBARRIER_WAIT_PARITY_RELAXED(mb_empty + 8 * slot, ph);
            const char* src = Wb + (size_t)(2 * P) * SITE_BYTES + rank * SLICE_BYTES;
            uint32_t dst = sb + slot * STAGE_BYTES + rank * SLICE_BYTES;
            if (elect_one()) {
                MBARRIER_EXPECT_TX(mb_full + 8 * slot, STAGE_BYTES);
                BULK_MC(dst, src, SLICE_BYTES, mb_full + 8 * slot, 0xF);
            }
            if (++slot == NST) { slot = 0; ph ^= 1; }
        }
    } else {
        // ---- 256 consumers: r = output index, q = l-quarter ----
        int r = tid & 63;
        int q = tid >> 6;
        float2* part = (float2*)(smem + OFF_P) + q * 64;
        int slot = 0, ph = 0;
        for (int P = 0; P < NPAIRS; P++) {
            MBARRIER_WAIT_PARITY(mb_full + 8 * slot, ph);
            #pragma unroll
            for (int sub = 0; sub < 2; sub++) {
                int s = 2 * P + sub;
                const float2* Wst = (const float2*)(smem + slot * STAGE_BYTES +
                                    sub * SITE_BYTES) + (q * 16) * 64 + r;
                float2 xs = xsh[side ? (511 - s) : s];
                const float4* v4 = (const float4*)(vb + (s & 1) * 64) + q * 4;
                float4 va = v4[0], vbq = v4[1], vc = v4[2], vd = v4[3];
                float a0 = 0.f, a1 = 0.f;
                #pragma unroll
                for (int j = 0; j < 4; j++) {
                    float2 w = Wst[j * 64];
                    float vv = (&va.x)[j];
                    a0 += vv * w.x; a1 += vv * w.y;
                }
                #pragma unroll
                for (int j = 0; j < 4; j++) {
                    float2 w = Wst[(4 + j) * 64];
                    float vv = (&vbq.x)[j];
                    a0 += vv * w.x; a1 += vv * w.y;
                }
                #pragma unroll
                for (int j = 0; j < 4; j++) {
                    float2 w = Wst[(8 + j) * 64];
                    float vv = (&vc.x)[j];
                    a0 += vv * w.x; a1 += vv * w.y;
                }
                #pragma unroll
                for (int j = 0; j < 4; j++) {
                    float2 w = Wst[(12 + j) * 64];
                    float vv = (&vd.x)[j];
                    a0 += vv * w.x; a1 += vv * w.y;
                }
                part[r] = make_float2(a0, a1);
                NAMED_BAR(1, CONS);
                if (q == 0) {
                    float2 p0 = part[r], p1 = part[r + 64],
                           p2 = part[r + 128], p3 = part[r + 192];
                    float s0 = (p0.x + p1.x) + (p2.x + p3.x);
                    float s1 = (p0.y + p1.y) + (p2.y + p3.y);
                    vb[((s & 1) ^ 1) * 64 + r] = xs.x * s0 + xs.y * s1;
                }
                NAMED_BAR(1, CONS);
            }
            if (tid < CLUSTER)   // stage consumed: release on all 4 producers
                MBARRIER_ARRIVE_CLUSTER(mb_empty + 8 * slot, tid);
            if (++slot == NST) { slot = 0; ph ^= 1; }
        }
        if (tid < 64) {          // 512 sites -> result back in vb[0..63]
            if (side) g_wR[b][tid] = vb[tid];
            else      g_vL[b][tid] = vb[tid];
        }
    }
    CLUSTER_SYNC();              // no early exit while peers multicast here
}

// ---------- output: out[b][o] = sum_l vL[l] * sum_r core[o][l][r] * wR[r] ----------
__global__ void __launch_bounds__(640, 1)
output_kernel(const float* __restrict__ core, float* __restrict__ out) {
    int b = blockIdx.x;
    int tid = threadIdx.x;          // 640 = 10 o * 64 l
    int o = tid >> 6, l = tid & 63;
    __shared__ float wsh[D_];
    __shared__ float red[O_][2];
    if (tid < 64) wsh[tid] = g_wR[b][tid];
    __syncthreads();
    const float4* c4 = (const float4*)(core + (o * D_ + l) * D_);
    const float4* w4 = (const float4*)wsh;
    float s = 0.f;
    #pragma unroll
    for (int k = 0; k < 16; k++) {
        float4 cv = c4[k], wv = w4[k];
        s += cv.x * wv.x + cv.y * wv.y + cv.z * wv.z + cv.w * wv.w;
    }
    s *= g_vL[b][l];
    #pragma unroll
    for (int off = 16; off; off >>= 1) s += __shfl_xor_sync(0xFFFFFFFFu, s, off);
    if ((tid & 31) == 0) red[o][(tid >> 5) & 1] = s;
    __syncthreads();
    if (tid < O_) out[b * O_ + tid] = red[tid][0] + red[tid][1];
}

extern "C" void kernel_launch(void* const* d_in, const int* in_sizes, int n_in,
                              void* d_out, int out_size) {
    const float* x    = (const float*)d_in[0];   // [64, 1024, 2]
    const float* Wl   = (const float*)d_in[1];   // [512, 64, 64, 2]
    const float* core = (const float*)d_in[2];   // [10, 64, 64]
    const float* Wr   = (const float*)d_in[3];   // [512, 64, 64, 2]
    float* out = (float*)d_out;                  // [64, 10]

    transpose_wr_kernel<<<L_, 256>>>(Wr);

    cudaFuncSetAttribute(chain_kernel,
                         cudaFuncAttributeMaxDynamicSharedMemorySize, SMEM_TOTAL);
    cudaLaunchConfig_t cfg = {};
    cfg.gridDim = dim3(128, 1, 1);
    cfg.blockDim = dim3(TOT, 1, 1);
    cfg.dynamicSmemBytes = SMEM_TOTAL;
    cfg.stream = 0;
    cudaLaunchAttribute at[1];
    at[0].id = cudaLaunchAttributeClusterDimension;
    at[0].val.clusterDim.x = CLUSTER;
    at[0].val.clusterDim.y = 1;
    at[0].val.clusterDim.z = 1;
    cfg.attrs = at;
    cfg.numAttrs = 1;
    cudaLaunchKernelEx(&cfg, chain_kernel, x, Wl);

    output_kernel<<<B_, 640>>>(core, out);
}